// round 5
// baseline (speedup 1.0000x reference)
#include <cuda_runtime.h>
#include <math.h>
#include <stdint.h>

#define B_  4
#define L_  2048
#define IN_ 1024
#define D_  512
#define DI  1024
#define DS  128
#define HD  64
#define KC  4
#define NH  16
#define CD  1280
#define DP  2320
#define NL  2
#define NC  2
#define M_  (B_*L_)   // 8192

// ---------------- scratch (static device globals; no runtime alloc) ------------
__device__ float g_h  [M_*D_];
__device__ float g_u  [M_*D_];
__device__ float g_zx [M_*DP];
__device__ float g_xbc[M_*CD];
__device__ float g_dt [M_*NH];
__device__ float g_dA [M_*NH];
__device__ float g_y  [M_*DI];

// ---------------- helpers ------------------------------------------------------
__device__ __forceinline__ float silu_f(float x) {
    return x / (1.f + __expf(-x));
}
__device__ __forceinline__ uint32_t f2tf32(float x) {
    uint32_t r;
    asm("cvt.rna.tf32.f32 %0, %1;" : "=r"(r) : "f"(x));
    return r;
}
__device__ __forceinline__ void split_tf32(float x, uint32_t& hi, uint32_t& lo) {
    hi = f2tf32(x);
    float hf = __uint_as_float(hi);
    lo = f2tf32(x - hf);
}
__device__ __forceinline__ void mma_tf32(float c[4], const uint32_t a[4], const uint32_t b[2]) {
    asm volatile(
        "mma.sync.aligned.m16n8k8.row.col.f32.tf32.tf32.f32 "
        "{%0,%1,%2,%3}, {%4,%5,%6,%7}, {%8,%9}, {%0,%1,%2,%3};"
        : "+f"(c[0]), "+f"(c[1]), "+f"(c[2]), "+f"(c[3])
        : "r"(a[0]), "r"(a[1]), "r"(a[2]), "r"(a[3]), "r"(b[0]), "r"(b[1]));
}

// ---------------- tensor-core GEMM: C[M,N] = A[M,K] @ W[N,K]^T (+epilogue) -----
// 3xTF32: split operands hi/lo, accumulate hi*hi + hi*lo + lo*hi in fp32.
// BM=BN=128, BK=16. 8 warps, each 64x32. EPI: 0 none, 1 +bias+GELU, 2 +residual.
template<int EPI>
__global__ __launch_bounds__(256) void gemm_tc(
    const float* __restrict__ A, const float* __restrict__ W,
    const float* __restrict__ bias, const float* __restrict__ res,
    float* __restrict__ C, int M, int N, int Kd)
{
    // k-pair interleave: index [ks][row][ (k&3)*2 + ((k>>2)&1) ] holds (k, k+4) adjacent
    __shared__ float AsH[2][128][8], AsL[2][128][8];
    __shared__ float BsH[2][128][8], BsL[2][128][8];

    const int tid  = threadIdx.x;
    const int bm   = blockIdx.y * 128;
    const int bn   = blockIdx.x * 128;
    const int warp = tid >> 5, lane = tid & 31;
    const int wm   = (warp >> 2) * 64;     // 0 or 64
    const int wn   = (warp & 3) * 32;      // 0,32,64,96
    const int g    = lane >> 2, tg = lane & 3;

    const int row  = tid >> 1;             // 0..127
    const int half = tid & 1;              // k-offset 8*half within BK=16
    const float* Ap = A + (size_t)(bm + row) * Kd + 8 * half;
    const bool  wv  = (bn + row) < N;
    const float* Wp = W + (size_t)(wv ? (bn + row) : 0) * Kd + 8 * half;

    float acc[4][4][4];
#pragma unroll
    for (int i = 0; i < 4; i++)
#pragma unroll
        for (int j = 0; j < 4; j++)
#pragma unroll
            for (int c = 0; c < 4; c++) acc[i][j][c] = 0.f;

    // prefetch stage 0
    float4 av0 = *(const float4*)(Ap);
    float4 av1 = *(const float4*)(Ap + 4);
    float4 wv0 = make_float4(0.f,0.f,0.f,0.f), wv1 = wv0;
    if (wv) { wv0 = *(const float4*)(Wp); wv1 = *(const float4*)(Wp + 4); }

    for (int k0 = 0; k0 < Kd; k0 += 16) {
        __syncthreads();
        // stage current regs into smem, splitting hi/lo
        {
            const float a0[4] = {av0.x, av0.y, av0.z, av0.w};
            const float a1[4] = {av1.x, av1.y, av1.z, av1.w};
            const float w0[4] = {wv0.x, wv0.y, wv0.z, wv0.w};
            const float w1[4] = {wv1.x, wv1.y, wv1.z, wv1.w};
#pragma unroll
            for (int j = 0; j < 4; j++) {
                uint32_t h, l;
                split_tf32(a0[j], h, l);
                AsH[half][row][2*j+0] = __uint_as_float(h);
                AsL[half][row][2*j+0] = __uint_as_float(l);
                split_tf32(a1[j], h, l);
                AsH[half][row][2*j+1] = __uint_as_float(h);
                AsL[half][row][2*j+1] = __uint_as_float(l);
                split_tf32(w0[j], h, l);
                BsH[half][row][2*j+0] = __uint_as_float(h);
                BsL[half][row][2*j+0] = __uint_as_float(l);
                split_tf32(w1[j], h, l);
                BsH[half][row][2*j+1] = __uint_as_float(h);
                BsL[half][row][2*j+1] = __uint_as_float(l);
            }
        }
        __syncthreads();
        // prefetch next stage while computing this one
        if (k0 + 16 < Kd) {
            av0 = *(const float4*)(Ap + k0 + 16);
            av1 = *(const float4*)(Ap + k0 + 20);
            if (wv) {
                wv0 = *(const float4*)(Wp + k0 + 16);
                wv1 = *(const float4*)(Wp + k0 + 20);
            }
        }
#pragma unroll
        for (int ks = 0; ks < 2; ks++) {
            uint32_t ah[4][4], al[4][4];
#pragma unroll
            for (int mt = 0; mt < 4; mt++) {
                const int r0 = wm + mt*16 + g;
                float2 p1 = *(const float2*)&AsH[ks][r0    ][tg*2];
                float2 p2 = *(const float2*)&AsH[ks][r0 + 8][tg*2];
                ah[mt][0] = __float_as_uint(p1.x); ah[mt][1] = __float_as_uint(p2.x);
                ah[mt][2] = __float_as_uint(p1.y); ah[mt][3] = __float_as_uint(p2.y);
                float2 q1 = *(const float2*)&AsL[ks][r0    ][tg*2];
                float2 q2 = *(const float2*)&AsL[ks][r0 + 8][tg*2];
                al[mt][0] = __float_as_uint(q1.x); al[mt][1] = __float_as_uint(q2.x);
                al[mt][2] = __float_as_uint(q1.y); al[mt][3] = __float_as_uint(q2.y);
            }
            uint32_t bh[4][2], bl[4][2];
#pragma unroll
            for (int nt = 0; nt < 4; nt++) {
                const int n0 = wn + nt*8 + g;
                float2 p = *(const float2*)&BsH[ks][n0][tg*2];
                bh[nt][0] = __float_as_uint(p.x); bh[nt][1] = __float_as_uint(p.y);
                float2 q = *(const float2*)&BsL[ks][n0][tg*2];
                bl[nt][0] = __float_as_uint(q.x); bl[nt][1] = __float_as_uint(q.y);
            }
#pragma unroll
            for (int mt = 0; mt < 4; mt++)
#pragma unroll
                for (int nt = 0; nt < 4; nt++) {
                    mma_tf32(acc[mt][nt], ah[mt], bh[nt]);
                    mma_tf32(acc[mt][nt], ah[mt], bl[nt]);
                    mma_tf32(acc[mt][nt], al[mt], bh[nt]);
                }
        }
    }

    // epilogue
#pragma unroll
    for (int mt = 0; mt < 4; mt++) {
#pragma unroll
        for (int nt = 0; nt < 4; nt++) {
            const int r = bm + wm + mt*16 + g;
            const int c = bn + wn + nt*8 + tg*2;
            if (c < N) {    // N even, c even -> pair fully valid
                float v[4] = {acc[mt][nt][0], acc[mt][nt][1],
                              acc[mt][nt][2], acc[mt][nt][3]};
                if (EPI == 1) {
                    const float b0 = bias[c], b1 = bias[c+1];
                    v[0] += b0; v[1] += b1; v[2] += b0; v[3] += b1;
#pragma unroll
                    for (int i = 0; i < 4; i++)
                        v[i] = 0.5f * v[i] * (1.f + erff(v[i] * 0.70710678118654752f));
                }
                if (EPI == 2) {
                    const float* r0 = res + (size_t)r * N + c;
                    const float* r1 = res + (size_t)(r+8) * N + c;
                    v[0] += r0[0]; v[1] += r0[1]; v[2] += r1[0]; v[3] += r1[1];
                }
                *(float2*)(C + (size_t)r     * N + c) = make_float2(v[0], v[1]);
                *(float2*)(C + (size_t)(r+8) * N + c) = make_float2(v[2], v[3]);
            }
        }
    }
}

// ---------------- LayerNorm over last dim (512) --------------------------------
__global__ __launch_bounds__(256) void ln_k(
    const float* __restrict__ x, const float* __restrict__ w,
    const float* __restrict__ b, float* __restrict__ o)
{
    __shared__ float red[256];
    const int row = blockIdx.x;
    const int tid = threadIdx.x;
    const float* xr = x + (size_t)row * D_;
    float v0 = xr[tid], v1 = xr[tid + 256];

    red[tid] = v0 + v1;
    __syncthreads();
    for (int st = 128; st > 0; st >>= 1) {
        if (tid < st) red[tid] += red[tid + st];
        __syncthreads();
    }
    const float mean = red[0] * (1.f / D_);
    __syncthreads();
    const float d0 = v0 - mean, d1 = v1 - mean;
    red[tid] = d0*d0 + d1*d1;
    __syncthreads();
    for (int st = 128; st > 0; st >>= 1) {
        if (tid < st) red[tid] += red[tid + st];
        __syncthreads();
    }
    const float rstd = rsqrtf(red[0] * (1.f / D_) + 1e-5f);
    float* orow = o + (size_t)row * D_;
    orow[tid]       = d0 * rstd * w[tid]       + b[tid];
    orow[tid + 256] = d1 * rstd * w[tid + 256] + b[tid + 256];
}

// ---------------- causal depthwise conv (K=4) + SiLU ---------------------------
__global__ void conv_k(const float* __restrict__ zx, const float* __restrict__ w,
                       const float* __restrict__ bias, float* __restrict__ out)
{
    const int idx = blockIdx.x * blockDim.x + threadIdx.x;
    if (idx >= M_ * CD) return;
    const int c = idx % CD;
    const int m = idx / CD;
    const int t = m % L_;
    float acc = bias[c];
#pragma unroll
    for (int k = 0; k < KC; k++) {
        const int tt = t + k - (KC - 1);
        if (tt >= 0)
            acc = fmaf(zx[(size_t)(m + k - (KC-1)) * DP + DI + c], w[c*KC + k], acc);
    }
    out[idx] = silu_f(acc);
}

// ---------------- dt = softplus(dt+bias); dA = exp(dt * -exp(A_log)) -----------
__global__ void dt_k(const float* __restrict__ zx, const float* __restrict__ dtb,
                     const float* __restrict__ Alog,
                     float* __restrict__ dt, float* __restrict__ dA)
{
    const int idx = blockIdx.x * blockDim.x + threadIdx.x;
    if (idx >= M_ * NH) return;
    const int hh = idx % NH;
    const int m  = idx / NH;
    const float v = zx[(size_t)m * DP + DI + CD + hh] + dtb[hh];
    const float sp = (v > 20.f) ? v : log1pf(expf(v));
    dt[idx] = sp;
    dA[idx] = expf(sp * -expf(Alog[hh]));
}

// ---------------- sequential SSM scan ------------------------------------------
__global__ __launch_bounds__(256) void scan_k(
    const float* __restrict__ xbc, const float* __restrict__ dt,
    const float* __restrict__ dA, const float* __restrict__ Dp,
    float* __restrict__ y)
{
    __shared__ float shB[DS], shC[DS], shX[32], red[256];
    const int psplit = blockIdx.x;
    const int h  = blockIdx.y;
    const int b  = blockIdx.z;
    const int tid = threadIdx.x;
    const int plocal = tid & 31;
    const int ngrp = tid >> 5;
    const int n0 = ngrp * 16;
    const int pg = psplit * 32 + plocal;
    const float Dv = Dp[h];

    float s[16];
#pragma unroll
    for (int j = 0; j < 16; j++) s[j] = 0.f;

    const size_t base = (size_t)b * L_;
    float rB = 0.f, rC = 0.f, rX = 0.f;
    {
        const float* p = xbc + base * CD;
        if (tid < DS) rB = p[DI + tid];
        else          rC = p[DI + DS + (tid - DS)];
        if (tid < 32) rX = p[h*HD + pg];
    }

    for (int t = 0; t < L_; t++) {
        __syncthreads();
        if (tid < DS) shB[tid] = rB; else shC[tid - DS] = rC;
        if (tid < 32) shX[tid] = rX;
        if (t + 1 < L_) {
            const float* p = xbc + (base + t + 1) * CD;
            if (tid < DS) rB = p[DI + tid];
            else          rC = p[DI + DS + (tid - DS)];
            if (tid < 32) rX = p[h*HD + pg];
        }
        const float dAv = dA[(base + t)*NH + h];
        const float dtv = dt[(base + t)*NH + h];
        __syncthreads();

        const float a = dtv * shX[plocal];
        float part = 0.f;
#pragma unroll
        for (int j = 0; j < 16; j++) {
            s[j] = fmaf(s[j], dAv, a * shB[n0 + j]);
            part = fmaf(s[j], shC[n0 + j], part);
        }
        red[ngrp*32 + plocal] = part;
        __syncthreads();
        if (tid < 32) {
            float acc = shX[tid] * Dv;
#pragma unroll
            for (int g2 = 0; g2 < 8; g2++) acc += red[g2*32 + tid];
            y[(base + t)*DI + h*HD + pg] = acc;
        }
    }
}

// ---------------- gating (y * silu(z)) + RMSNorm * gnorm_w ---------------------
__global__ __launch_bounds__(256) void gate_k(
    const float* __restrict__ zx, const float* __restrict__ gw,
    float* __restrict__ y)
{
    __shared__ float red[256];
    const int row = blockIdx.x;
    const int tid = threadIdx.x;
    const float* zr = zx + (size_t)row * DP;
    float* yr = y + (size_t)row * DI;
    float g[4]; float ss = 0.f;
#pragma unroll
    for (int i = 0; i < 4; i++) {
        const int c = tid + i*256;
        const float z = zr[c];
        const float gv = yr[c] * silu_f(z);
        g[i] = gv; ss += gv * gv;
    }
    red[tid] = ss;
    __syncthreads();
    for (int st = 128; st > 0; st >>= 1) {
        if (tid < st) red[tid] += red[tid + st];
        __syncthreads();
    }
    const float scale = rsqrtf(red[0] * (1.f / DI) + 1e-5f);
#pragma unroll
    for (int i = 0; i < 4; i++) {
        const int c = tid + i*256;
        yr[c] = g[i] * scale * gw[c];
    }
}

// ---------------- classifier ---------------------------------------------------
__global__ void cls_k(const float* __restrict__ h, const float* __restrict__ w,
                      const float* __restrict__ b, float* __restrict__ out)
{
    const int gwarp = (blockIdx.x * blockDim.x + threadIdx.x) >> 5;
    const int lane = threadIdx.x & 31;
    if (gwarp >= M_) return;
    const float* hr = h + (size_t)gwarp * D_;
    float a0 = 0.f, a1 = 0.f;
    for (int k = lane; k < D_; k += 32) {
        const float hv = hr[k];
        a0 = fmaf(hv, w[k],      a0);
        a1 = fmaf(hv, w[D_ + k], a1);
    }
    for (int off = 16; off; off >>= 1) {
        a0 += __shfl_xor_sync(0xFFFFFFFFu, a0, off);
        a1 += __shfl_xor_sync(0xFFFFFFFFu, a1, off);
    }
    if (lane == 0) {
        out[gwarp*2 + 0] = a0 + b[0];
        out[gwarp*2 + 1] = a1 + b[1];
    }
}

// ---------------- launch -------------------------------------------------------
extern "C" void kernel_launch(void* const* d_in, const int* in_sizes, int n_in,
                              void* d_out, int out_size)
{
    const float* x      = (const float*)d_in[0];
    const float* fc1_w  = (const float*)d_in[1];
    const float* fc1_b  = (const float*)d_in[2];
    const float* ln_w   = (const float*)d_in[3];
    const float* ln_b   = (const float*)d_in[4];
    const float* in_w   = (const float*)d_in[5];
    const float* conv_w = (const float*)d_in[6];
    const float* conv_b = (const float*)d_in[7];
    const float* dt_b   = (const float*)d_in[8];
    const float* A_log  = (const float*)d_in[9];
    const float* D_p    = (const float*)d_in[10];
    const float* gn_w   = (const float*)d_in[11];
    const float* out_w  = (const float*)d_in[12];
    const float* cls_w  = (const float*)d_in[13];
    const float* cls_b  = (const float*)d_in[14];
    float* out = (float*)d_out;

    float *h, *u, *zx, *xbc, *dtp, *dAp, *y;
    cudaGetSymbolAddress((void**)&h,   g_h);
    cudaGetSymbolAddress((void**)&u,   g_u);
    cudaGetSymbolAddress((void**)&zx,  g_zx);
    cudaGetSymbolAddress((void**)&xbc, g_xbc);
    cudaGetSymbolAddress((void**)&dtp, g_dt);
    cudaGetSymbolAddress((void**)&dAp, g_dA);
    cudaGetSymbolAddress((void**)&y,   g_y);

    gemm_tc<1><<<dim3(D_/128, M_/128), 256>>>(x, fc1_w, fc1_b, nullptr, h, M_, D_, IN_);

    for (int l = 0; l < NL; l++) {
        ln_k<<<M_, 256>>>(h, ln_w + l*D_, ln_b + l*D_, u);
        gemm_tc<0><<<dim3((DP + 127)/128, M_/128), 256>>>(
            u, in_w + (size_t)l*DP*D_, nullptr, nullptr, zx, M_, DP, D_);
        conv_k<<<(M_*CD + 255)/256, 256>>>(zx, conv_w + l*CD*KC, conv_b + l*CD, xbc);
        dt_k<<<(M_*NH + 255)/256, 256>>>(zx, dt_b + l*NH, A_log + l*NH, dtp, dAp);
        scan_k<<<dim3(2, NH, B_), 256>>>(xbc, dtp, dAp, D_p + l*NH, y);
        gate_k<<<M_, 256>>>(zx, gn_w + l*DI, y);
        gemm_tc<2><<<dim3(D_/128, M_/128), 256>>>(
            y, out_w + (size_t)l*D_*DI, nullptr, h, h, M_, D_, DI);
    }

    cls_k<<<(M_*32 + 255)/256, 256>>>(h, cls_w, cls_b, out);
}

// round 7
// speedup vs baseline: 1.3773x; 1.3773x over previous
#include <cuda_runtime.h>
#include <cuda_bf16.h>
#include <math.h>
#include <stdint.h>

#define B_  4
#define L_  2048
#define IN_ 1024
#define D_  512
#define DI  1024
#define DS  128
#define HD  64
#define KC  4
#define NH  16
#define CD  1280
#define DP  2320
#define NL  2
#define NC  2
#define M_  (B_*L_)   // 8192

// ---------------- scratch (static device globals; no runtime alloc) ------------
__device__ float g_h  [M_*D_];
__device__ float g_zx [M_*DP];
__device__ float g_xbc[M_*CD];
__device__ float g_dt [M_*NH];
__device__ float g_dA [M_*NH];
__device__ float g_y  [M_*DI];

// bf16 hi/lo packed (2 bf16 per uint32, consecutive k)
__device__ uint32_t g_xH [M_*IN_/2], g_xL [M_*IN_/2];
__device__ uint32_t g_uH [M_*D_/2],  g_uL [M_*D_/2];
__device__ uint32_t g_yH [M_*DI/2],  g_yL [M_*DI/2];
__device__ uint32_t g_w1H[D_*IN_/2], g_w1L[D_*IN_/2];
__device__ uint32_t g_wiH[NL*DP*D_/2], g_wiL[NL*DP*D_/2];
__device__ uint32_t g_woH[NL*D_*DI/2], g_woL[NL*D_*DI/2];

// ---------------- helpers ------------------------------------------------------
__device__ __forceinline__ float silu_f(float x) {
    return x / (1.f + __expf(-x));
}
__device__ __forceinline__ void pack_hl(float x0, float x1, uint32_t& H, uint32_t& L) {
    __nv_bfloat16 h0 = __float2bfloat16(x0);
    __nv_bfloat16 h1 = __float2bfloat16(x1);
    __nv_bfloat16 l0 = __float2bfloat16(x0 - __bfloat162float(h0));
    __nv_bfloat16 l1 = __float2bfloat16(x1 - __bfloat162float(h1));
    H = (uint32_t)__bfloat16_as_ushort(h0) | ((uint32_t)__bfloat16_as_ushort(h1) << 16);
    L = (uint32_t)__bfloat16_as_ushort(l0) | ((uint32_t)__bfloat16_as_ushort(l1) << 16);
}
__device__ __forceinline__ void mma_bf16(float c[4], const uint32_t a[4], const uint32_t b[2]) {
    asm volatile(
        "mma.sync.aligned.m16n8k16.row.col.f32.bf16.bf16.f32 "
        "{%0,%1,%2,%3}, {%4,%5,%6,%7}, {%8,%9}, {%0,%1,%2,%3};"
        : "+f"(c[0]), "+f"(c[1]), "+f"(c[2]), "+f"(c[3])
        : "r"(a[0]), "r"(a[1]), "r"(a[2]), "r"(a[3]), "r"(b[0]), "r"(b[1]));
}

// ---------------- generic fp32 -> bf16 hi/lo pack converter --------------------
__global__ void cvt_k(const float* __restrict__ s, uint32_t* __restrict__ H,
                      uint32_t* __restrict__ L, int npairs)
{
    const int i = blockIdx.x * blockDim.x + threadIdx.x;
    if (i >= npairs) return;
    const float2 v = ((const float2*)s)[i];
    uint32_t h, l;
    pack_hl(v.x, v.y, h, l);
    H[i] = h; L[i] = l;
}

// ---------------- bf16 3x tensor-core GEMM -------------------------------------
// C[M,N] = A[M,K] @ W[N,K]^T with A,W given as packed bf16 hi/lo pairs.
// acc += aH*bH + aH*bL + aL*bH  (drops lo*lo ~ 2^-16 relative).
// BM=BN=128, BK=32. 8 warps, each 64x32. EPI: 0 none, 1 +bias+GELU, 2 +residual.
#define SPAD 20
template<int EPI>
__global__ __launch_bounds__(256) void gemm_bf3(
    const uint32_t* __restrict__ AH, const uint32_t* __restrict__ AL,
    const uint32_t* __restrict__ WH, const uint32_t* __restrict__ WL,
    const float* __restrict__ bias, const float* __restrict__ res,
    float* __restrict__ C, int M, int N, int Kd)
{
    __shared__ uint32_t sAH[128][SPAD], sAL[128][SPAD];
    __shared__ uint32_t sBH[128][SPAD], sBL[128][SPAD];

    const int K2   = Kd >> 1;             // u32 pairs per row
    const int tid  = threadIdx.x;
    const int bm   = blockIdx.y * 128;
    const int bn   = blockIdx.x * 128;
    const int warp = tid >> 5, lane = tid & 31;
    const int wm   = (warp >> 2) * 64;    // 0 or 64
    const int wn   = (warp & 3) * 32;     // 0,32,64,96
    const int g    = lane >> 2, tg = lane & 3;

    const int row  = tid >> 1;            // 0..127
    const int half = tid & 1;             // pair-offset 8*half within BK-pairs=16
    const uint32_t* pAH = AH + (size_t)(bm + row) * K2 + half * 8;
    const uint32_t* pAL = AL + (size_t)(bm + row) * K2 + half * 8;
    const bool wv = (bn + row) < N;
    const size_t wrow = (size_t)(wv ? (bn + row) : 0) * K2 + half * 8;
    const uint32_t* pWH = WH + wrow;
    const uint32_t* pWL = WL + wrow;

    float acc[4][4][4];
#pragma unroll
    for (int i = 0; i < 4; i++)
#pragma unroll
        for (int j = 0; j < 4; j++)
#pragma unroll
            for (int c = 0; c < 4; c++) acc[i][j][c] = 0.f;

    const uint4 zero4 = make_uint4(0u,0u,0u,0u);
    // prefetch stage 0
    uint4 rah0 = *(const uint4*)(pAH);
    uint4 rah1 = *(const uint4*)(pAH + 4);
    uint4 ral0 = *(const uint4*)(pAL);
    uint4 ral1 = *(const uint4*)(pAL + 4);
    uint4 rbh0 = zero4, rbh1 = zero4, rbl0 = zero4, rbl1 = zero4;
    if (wv) {
        rbh0 = *(const uint4*)(pWH);
        rbh1 = *(const uint4*)(pWH + 4);
        rbl0 = *(const uint4*)(pWL);
        rbl1 = *(const uint4*)(pWL + 4);
    }

    for (int k0 = 0; k0 < K2; k0 += 16) {
        __syncthreads();
        ((uint4*)&sAH[row][half*8])[0] = rah0;
        ((uint4*)&sAH[row][half*8])[1] = rah1;
        ((uint4*)&sAL[row][half*8])[0] = ral0;
        ((uint4*)&sAL[row][half*8])[1] = ral1;
        ((uint4*)&sBH[row][half*8])[0] = rbh0;
        ((uint4*)&sBH[row][half*8])[1] = rbh1;
        ((uint4*)&sBL[row][half*8])[0] = rbl0;
        ((uint4*)&sBL[row][half*8])[1] = rbl1;
        __syncthreads();
        if (k0 + 16 < K2) {
            rah0 = *(const uint4*)(pAH + k0 + 16);
            rah1 = *(const uint4*)(pAH + k0 + 20);
            ral0 = *(const uint4*)(pAL + k0 + 16);
            ral1 = *(const uint4*)(pAL + k0 + 20);
            if (wv) {
                rbh0 = *(const uint4*)(pWH + k0 + 16);
                rbh1 = *(const uint4*)(pWH + k0 + 20);
                rbl0 = *(const uint4*)(pWL + k0 + 16);
                rbl1 = *(const uint4*)(pWL + k0 + 20);
            }
        }
#pragma unroll
        for (int ks = 0; ks < 2; ks++) {
            const int kc = ks * 8;
            uint32_t bh[4][2], bl[4][2];
#pragma unroll
            for (int nt = 0; nt < 4; nt++) {
                const int n0 = wn + nt*8 + g;
                bh[nt][0] = sBH[n0][kc + tg];
                bh[nt][1] = sBH[n0][kc + tg + 4];
                bl[nt][0] = sBL[n0][kc + tg];
                bl[nt][1] = sBL[n0][kc + tg + 4];
            }
#pragma unroll
            for (int mt = 0; mt < 4; mt++) {
                const int r0 = wm + mt*16 + g;
                uint32_t ah[4], al[4];
                ah[0] = sAH[r0    ][kc + tg];
                ah[1] = sAH[r0 + 8][kc + tg];
                ah[2] = sAH[r0    ][kc + tg + 4];
                ah[3] = sAH[r0 + 8][kc + tg + 4];
                al[0] = sAL[r0    ][kc + tg];
                al[1] = sAL[r0 + 8][kc + tg];
                al[2] = sAL[r0    ][kc + tg + 4];
                al[3] = sAL[r0 + 8][kc + tg + 4];
#pragma unroll
                for (int nt = 0; nt < 4; nt++) {
                    mma_bf16(acc[mt][nt], ah, bh[nt]);
                    mma_bf16(acc[mt][nt], ah, bl[nt]);
                    mma_bf16(acc[mt][nt], al, bh[nt]);
                }
            }
        }
    }

    // epilogue
#pragma unroll
    for (int mt = 0; mt < 4; mt++) {
#pragma unroll
        for (int nt = 0; nt < 4; nt++) {
            const int r = bm + wm + mt*16 + g;
            const int c = bn + wn + nt*8 + tg*2;
            if (c < N) {
                float v[4] = {acc[mt][nt][0], acc[mt][nt][1],
                              acc[mt][nt][2], acc[mt][nt][3]};
                if (EPI == 1) {
                    const float b0 = bias[c], b1 = bias[c+1];
                    v[0] += b0; v[1] += b1; v[2] += b0; v[3] += b1;
#pragma unroll
                    for (int i = 0; i < 4; i++)
                        v[i] = 0.5f * v[i] * (1.f + erff(v[i] * 0.70710678118654752f));
                }
                if (EPI == 2) {
                    const float* r0 = res + (size_t)r * N + c;
                    const float* r1 = res + (size_t)(r+8) * N + c;
                    v[0] += r0[0]; v[1] += r0[1]; v[2] += r1[0]; v[3] += r1[1];
                }
                *(float2*)(C + (size_t)r     * N + c) = make_float2(v[0], v[1]);
                *(float2*)(C + (size_t)(r+8) * N + c) = make_float2(v[2], v[3]);
            }
        }
    }
}

// ---------------- LayerNorm (512) -> packed bf16 hi/lo -------------------------
__global__ __launch_bounds__(256) void ln_k(
    const float* __restrict__ x, const float* __restrict__ w,
    const float* __restrict__ b, uint32_t* __restrict__ uH,
    uint32_t* __restrict__ uL)
{
    __shared__ float red[256];
    const int row = blockIdx.x;
    const int tid = threadIdx.x;
    const float2 v = ((const float2*)(x + (size_t)row * D_))[tid];

    red[tid] = v.x + v.y;
    __syncthreads();
    for (int st = 128; st > 0; st >>= 1) {
        if (tid < st) red[tid] += red[tid + st];
        __syncthreads();
    }
    const float mean = red[0] * (1.f / D_);
    __syncthreads();
    const float d0 = v.x - mean, d1 = v.y - mean;
    red[tid] = d0*d0 + d1*d1;
    __syncthreads();
    for (int st = 128; st > 0; st >>= 1) {
        if (tid < st) red[tid] += red[tid + st];
        __syncthreads();
    }
    const float rstd = rsqrtf(red[0] * (1.f / D_) + 1e-5f);
    const float2 wv = ((const float2*)w)[tid];
    const float2 bv = ((const float2*)b)[tid];
    uint32_t H, L;
    pack_hl(d0 * rstd * wv.x + bv.x, d1 * rstd * wv.y + bv.y, H, L);
    uH[(size_t)row * (D_/2) + tid] = H;
    uL[(size_t)row * (D_/2) + tid] = L;
}

// ---------------- causal depthwise conv (K=4) + SiLU ---------------------------
__global__ void conv_k(const float* __restrict__ zx, const float* __restrict__ w,
                       const float* __restrict__ bias, float* __restrict__ out)
{
    const int idx = blockIdx.x * blockDim.x + threadIdx.x;
    if (idx >= M_ * CD) return;
    const int c = idx % CD;
    const int m = idx / CD;
    const int t = m % L_;
    float acc = bias[c];
#pragma unroll
    for (int k = 0; k < KC; k++) {
        const int tt = t + k - (KC - 1);
        if (tt >= 0)
            acc = fmaf(zx[(size_t)(m + k - (KC-1)) * DP + DI + c], w[c*KC + k], acc);
    }
    out[idx] = silu_f(acc);
}

// ---------------- dt = softplus(dt+bias); dA = exp(dt * -exp(A_log)) -----------
__global__ void dt_k(const float* __restrict__ zx, const float* __restrict__ dtb,
                     const float* __restrict__ Alog,
                     float* __restrict__ dt, float* __restrict__ dA)
{
    const int idx = blockIdx.x * blockDim.x + threadIdx.x;
    if (idx >= M_ * NH) return;
    const int hh = idx % NH;
    const int m  = idx / NH;
    const float v = zx[(size_t)m * DP + DI + CD + hh] + dtb[hh];
    const float sp = (v > 20.f) ? v : log1pf(expf(v));
    dt[idx] = sp;
    dA[idx] = expf(sp * -expf(Alog[hh]));
}

// ---------------- sequential SSM scan ------------------------------------------
__global__ __launch_bounds__(256) void scan_k(
    const float* __restrict__ xbc, const float* __restrict__ dt,
    const float* __restrict__ dA, const float* __restrict__ Dp,
    float* __restrict__ y)
{
    __shared__ float shB[DS], shC[DS], shX[32], red[256];
    const int psplit = blockIdx.x;
    const int h  = blockIdx.y;
    const int b  = blockIdx.z;
    const int tid = threadIdx.x;
    const int plocal = tid & 31;
    const int ngrp = tid >> 5;
    const int n0 = ngrp * 16;
    const int pg = psplit * 32 + plocal;
    const float Dv = Dp[h];

    float s[16];
#pragma unroll
    for (int j = 0; j < 16; j++) s[j] = 0.f;

    const size_t base = (size_t)b * L_;
    float rB = 0.f, rC = 0.f, rX = 0.f;
    {
        const float* p = xbc + base * CD;
        if (tid < DS) rB = p[DI + tid];
        else          rC = p[DI + DS + (tid - DS)];
        if (tid < 32) rX = p[h*HD + pg];
    }

    for (int t = 0; t < L_; t++) {
        __syncthreads();
        if (tid < DS) shB[tid] = rB; else shC[tid - DS] = rC;
        if (tid < 32) shX[tid] = rX;
        if (t + 1 < L_) {
            const float* p = xbc + (base + t + 1) * CD;
            if (tid < DS) rB = p[DI + tid];
            else          rC = p[DI + DS + (tid - DS)];
            if (tid < 32) rX = p[h*HD + pg];
        }
        const float dAv = dA[(base + t)*NH + h];
        const float dtv = dt[(base + t)*NH + h];
        __syncthreads();

        const float a = dtv * shX[plocal];
        float part = 0.f;
#pragma unroll
        for (int j = 0; j < 16; j++) {
            s[j] = fmaf(s[j], dAv, a * shB[n0 + j]);
            part = fmaf(s[j], shC[n0 + j], part);
        }
        red[ngrp*32 + plocal] = part;
        __syncthreads();
        if (tid < 32) {
            float acc = shX[tid] * Dv;
#pragma unroll
            for (int g2 = 0; g2 < 8; g2++) acc += red[g2*32 + tid];
            y[(base + t)*DI + h*HD + pg] = acc;
        }
    }
}

// ---------------- gating + RMSNorm -> packed bf16 hi/lo ------------------------
__global__ __launch_bounds__(256) void gate_k(
    const float* __restrict__ zx, const float* __restrict__ gw,
    const float* __restrict__ y, uint32_t* __restrict__ yH,
    uint32_t* __restrict__ yL)
{
    __shared__ float red[256];
    const int row = blockIdx.x;
    const int tid = threadIdx.x;
    const float2* zr = (const float2*)(zx + (size_t)row * DP);
    const float2* yr = (const float2*)(y + (size_t)row * DI);
    float g0[2], g1[2]; float ss = 0.f;
#pragma unroll
    for (int i = 0; i < 2; i++) {
        const int p = tid + i*256;
        const float2 z2 = zr[p];
        const float2 y2 = yr[p];
        const float a = y2.x * silu_f(z2.x);
        const float b = y2.y * silu_f(z2.y);
        g0[i] = a; g1[i] = b; ss += a*a + b*b;
    }
    red[tid] = ss;
    __syncthreads();
    for (int st = 128; st > 0; st >>= 1) {
        if (tid < st) red[tid] += red[tid + st];
        __syncthreads();
    }
    const float scale = rsqrtf(red[0] * (1.f / DI) + 1e-5f);
#pragma unroll
    for (int i = 0; i < 2; i++) {
        const int p = tid + i*256;
        const float2 gv = ((const float2*)gw)[p];
        uint32_t H, L;
        pack_hl(g0[i] * scale * gv.x, g1[i] * scale * gv.y, H, L);
        yH[(size_t)row * (DI/2) + p] = H;
        yL[(size_t)row * (DI/2) + p] = L;
    }
}

// ---------------- classifier ---------------------------------------------------
__global__ void cls_k(const float* __restrict__ h, const float* __restrict__ w,
                      const float* __restrict__ b, float* __restrict__ out)
{
    const int gwarp = (blockIdx.x * blockDim.x + threadIdx.x) >> 5;
    const int lane = threadIdx.x & 31;
    if (gwarp >= M_) return;
    const float* hr = h + (size_t)gwarp * D_;
    float a0 = 0.f, a1 = 0.f;
    for (int k = lane; k < D_; k += 32) {
        const float hv = hr[k];
        a0 = fmaf(hv, w[k],      a0);
        a1 = fmaf(hv, w[D_ + k], a1);
    }
    for (int off = 16; off; off >>= 1) {
        a0 += __shfl_xor_sync(0xFFFFFFFFu, a0, off);
        a1 += __shfl_xor_sync(0xFFFFFFFFu, a1, off);
    }
    if (lane == 0) {
        out[gwarp*2 + 0] = a0 + b[0];
        out[gwarp*2 + 1] = a1 + b[1];
    }
}

// ---------------- launch -------------------------------------------------------
extern "C" void kernel_launch(void* const* d_in, const int* in_sizes, int n_in,
                              void* d_out, int out_size)
{
    const float* x      = (const float*)d_in[0];
    const float* fc1_w  = (const float*)d_in[1];
    const float* fc1_b  = (const float*)d_in[2];
    const float* ln_w   = (const float*)d_in[3];
    const float* ln_b   = (const float*)d_in[4];
    const float* in_w   = (const float*)d_in[5];
    const float* conv_w = (const float*)d_in[6];
    const float* conv_b = (const float*)d_in[7];
    const float* dt_b   = (const float*)d_in[8];
    const float* A_log  = (const float*)d_in[9];
    const float* D_p    = (const float*)d_in[10];
    const float* gn_w   = (const float*)d_in[11];
    const float* out_w  = (const float*)d_in[12];
    const float* cls_w  = (const float*)d_in[13];
    const float* cls_b  = (const float*)d_in[14];
    float* out = (float*)d_out;

    float *h, *zx, *xbc, *dtp, *dAp, *y;
    uint32_t *xH, *xL, *uH, *uL, *yH, *yL;
    uint32_t *w1H, *w1L, *wiH, *wiL, *woH, *woL;
    cudaGetSymbolAddress((void**)&h,   g_h);
    cudaGetSymbolAddress((void**)&zx,  g_zx);
    cudaGetSymbolAddress((void**)&xbc, g_xbc);
    cudaGetSymbolAddress((void**)&dtp, g_dt);
    cudaGetSymbolAddress((void**)&dAp, g_dA);
    cudaGetSymbolAddress((void**)&y,   g_y);
    cudaGetSymbolAddress((void**)&xH,  g_xH);
    cudaGetSymbolAddress((void**)&xL,  g_xL);
    cudaGetSymbolAddress((void**)&uH,  g_uH);
    cudaGetSymbolAddress((void**)&uL,  g_uL);
    cudaGetSymbolAddress((void**)&yH,  g_yH);
    cudaGetSymbolAddress((void**)&yL,  g_yL);
    cudaGetSymbolAddress((void**)&w1H, g_w1H);
    cudaGetSymbolAddress((void**)&w1L, g_w1L);
    cudaGetSymbolAddress((void**)&wiH, g_wiH);
    cudaGetSymbolAddress((void**)&wiL, g_wiL);
    cudaGetSymbolAddress((void**)&woH, g_woH);
    cudaGetSymbolAddress((void**)&woL, g_woL);

    // weight + input conversions (cheap, memory-bound)
    { int n = D_*IN_/2;      cvt_k<<<(n+255)/256, 256>>>(fc1_w, w1H, w1L, n); }
    { int n = NL*DP*D_/2;    cvt_k<<<(n+255)/256, 256>>>(in_w,  wiH, wiL, n); }
    { int n = NL*D_*DI/2;    cvt_k<<<(n+255)/256, 256>>>(out_w, woH, woL, n); }
    { int n = M_*IN_/2;      cvt_k<<<(n+255)/256, 256>>>(x,     xH,  xL,  n); }

    // fc1 + GELU
    gemm_bf3<1><<<dim3(D_/128, M_/128), 256>>>(
        xH, xL, w1H, w1L, fc1_b, nullptr, h, M_, D_, IN_);

    for (int l = 0; l < NL; l++) {
        ln_k<<<M_, 256>>>(h, ln_w + l*D_, ln_b + l*D_, uH, uL);
        gemm_bf3<0><<<dim3((DP + 127)/128, M_/128), 256>>>(
            uH, uL, wiH + (size_t)l*DP*(D_/2), wiL + (size_t)l*DP*(D_/2),
            nullptr, nullptr, zx, M_, DP, D_);
        conv_k<<<(M_*CD + 255)/256, 256>>>(zx, conv_w + l*CD*KC, conv_b + l*CD, xbc);
        dt_k<<<(M_*NH + 255)/256, 256>>>(zx, dt_b + l*NH, A_log + l*NH, dtp, dAp);
        scan_k<<<dim3(2, NH, B_), 256>>>(xbc, dtp, dAp, D_p + l*NH, y);
        gate_k<<<M_, 256>>>(zx, gn_w + l*DI, y, yH, yL);
        gemm_bf3<2><<<dim3(D_/128, M_/128), 256>>>(
            yH, yL, woH + (size_t)l*D_*(DI/2), woL + (size_t)l*D_*(DI/2),
            nullptr, h, h, M_, D_, DI);
    }

    cls_k<<<(M_*32 + 255)/256, 256>>>(h, cls_w, cls_b, out);
}

// round 16
// speedup vs baseline: 1.4795x; 1.0743x over previous
#include <cuda_runtime.h>
#include <cuda_bf16.h>
#include <math.h>
#include <stdint.h>

#define B_  4
#define L_  2048
#define IN_ 1024
#define D_  512
#define DI  1024
#define DS  128
#define HD  64
#define KC  4
#define NH  16
#define CD  1280
#define DP  2320
#define NL  2
#define NC  2
#define M_  (B_*L_)   // 8192

// ---------------- scratch (static device globals; no runtime alloc) ------------
__device__ float g_h  [M_*D_];
__device__ float g_zx [M_*DP];
__device__ float g_xbc[M_*CD];
__device__ float g_dt [M_*NH];
__device__ float g_dA [M_*NH];
__device__ float g_y  [M_*DI];

// bf16 hi/lo packed (2 bf16 per uint32, consecutive k)
__device__ uint32_t g_xH [M_*IN_/2], g_xL [M_*IN_/2];
__device__ uint32_t g_uH [M_*D_/2],  g_uL [M_*D_/2];
__device__ uint32_t g_yH [M_*DI/2],  g_yL [M_*DI/2];
__device__ uint32_t g_w1H[D_*IN_/2], g_w1L[D_*IN_/2];
__device__ uint32_t g_wiH[NL*DP*D_/2], g_wiL[NL*DP*D_/2];
__device__ uint32_t g_woH[NL*D_*DI/2], g_woL[NL*D_*DI/2];

// ---------------- helpers ------------------------------------------------------
__device__ __forceinline__ float silu_f(float x) {
    return x / (1.f + __expf(-x));
}
__device__ __forceinline__ void pack_hl(float x0, float x1, uint32_t& H, uint32_t& L) {
    __nv_bfloat16 h0 = __float2bfloat16(x0);
    __nv_bfloat16 h1 = __float2bfloat16(x1);
    __nv_bfloat16 l0 = __float2bfloat16(x0 - __bfloat162float(h0));
    __nv_bfloat16 l1 = __float2bfloat16(x1 - __bfloat162float(h1));
    H = (uint32_t)__bfloat16_as_ushort(h0) | ((uint32_t)__bfloat16_as_ushort(h1) << 16);
    L = (uint32_t)__bfloat16_as_ushort(l0) | ((uint32_t)__bfloat16_as_ushort(l1) << 16);
}
__device__ __forceinline__ void mma_bf16(float c[4], const uint32_t a[4], const uint32_t b[2]) {
    asm volatile(
        "mma.sync.aligned.m16n8k16.row.col.f32.bf16.bf16.f32 "
        "{%0,%1,%2,%3}, {%4,%5,%6,%7}, {%8,%9}, {%0,%1,%2,%3};"
        : "+f"(c[0]), "+f"(c[1]), "+f"(c[2]), "+f"(c[3])
        : "r"(a[0]), "r"(a[1]), "r"(a[2]), "r"(a[3]), "r"(b[0]), "r"(b[1]));
}
__device__ __forceinline__ uint32_t smem_u32(const void* p) {
    uint32_t a;
    asm("{ .reg .u64 t; cvta.to.shared.u64 t, %1; cvt.u32.u64 %0, t; }"
        : "=r"(a) : "l"(p));
    return a;
}
__device__ __forceinline__ void ldsm4(uint32_t* r, uint32_t addr) {
    asm volatile("ldmatrix.sync.aligned.m8n8.x4.shared.b16 {%0,%1,%2,%3}, [%4];"
                 : "=r"(r[0]), "=r"(r[1]), "=r"(r[2]), "=r"(r[3]) : "r"(addr));
}

// ---------------- generic fp32 -> bf16 hi/lo pack converter --------------------
__global__ void cvt_k(const float* __restrict__ s, uint32_t* __restrict__ H,
                      uint32_t* __restrict__ L, int npairs)
{
    const int i = blockIdx.x * blockDim.x + threadIdx.x;
    if (i >= npairs) return;
    const float2 v = ((const float2*)s)[i];
    uint32_t h, l;
    pack_hl(v.x, v.y, h, l);
    H[i] = h; L[i] = l;
}

// ---------------- ldmatrix bf16 3-term tensor-core GEMM ------------------------
// C[M,N] = A[M,K] @ W[N,K]^T, operands as packed bf16 hi/lo (2 bf16 / u32).
// acc += aH*bH + aH*bL + aL*bH.
// BM=BN=128, BK=32 elems (16 u32 = 4 chunks of 16B per row). 8 warps, 64x32 each.
// Swizzle: physical chunk = logical chunk ^ ((row>>1)&3).
//   - 2-bit XOR keeps offsets in-bounds (chunk 0..3).
//   - LDSM phase (8 rows, fixed logical chunk): banks 16*(row&1) + 4*(c^((row>>1)&3))
//     -> all 8 distinct 4-bank groups -> conflict-free.
//   - STS.128 phase (rows r,r+1 x chunks 0..3) covers banks 0..31 once.
// EPI: 0 none, 1 +bias+GELU, 2 +residual.
template<int EPI>
__global__ __launch_bounds__(256, 1) void gemm_ls(
    const uint32_t* __restrict__ AH, const uint32_t* __restrict__ AL,
    const uint32_t* __restrict__ WH, const uint32_t* __restrict__ WL,
    const float* __restrict__ bias, const float* __restrict__ res,
    float* __restrict__ C, int M, int N, int Kd)
{
    __shared__ uint32_t sm[4][128 * 16];

    const int tid  = threadIdx.x;
    const int lane = tid & 31, warp = tid >> 5;
    const int bm   = blockIdx.y * 128, bn = blockIdx.x * 128;
    const int K2   = Kd >> 1;
    const int wm   = (warp >> 2) * 64;    // 0 / 64
    const int wn   = (warp & 3) * 32;     // 0,32,64,96
    const int g    = lane >> 2, tg = lane & 3;

    const uint32_t sb = smem_u32(sm);

    // ldmatrix byte offsets within a tile, per ks (16-elem sub-chunk)
    const int arow = wm + (lane & 15);
    const int ahi  = lane >> 4;           // 0/1: k-halves
    const int axor = (arow >> 1) & 3;
    uint32_t aoff[2];
#pragma unroll
    for (int ks = 0; ks < 2; ks++)
        aoff[ks] = (uint32_t)(arow * 64 + (((ks*2 + ahi) ^ axor) << 4));
    const int bsel = (lane >> 3) & 1;
    const int brow = wn + (lane & 7) + (lane >> 4) * 8;
    uint32_t boff[2][2];  // [pr][ks]
#pragma unroll
    for (int pr = 0; pr < 2; pr++) {
        const int br = brow + pr * 16;
        const int bxor = (br >> 1) & 3;
#pragma unroll
        for (int ks = 0; ks < 2; ks++)
            boff[pr][ks] = (uint32_t)(br * 64 + (((ks*2 + bsel) ^ bxor) << 4));
    }

    // store-side mapping: slot = tid + it*256 -> row = tid/4 + it*64, q = tid&3
    const int q    = tid & 3;
    const int row0 = tid >> 2;
    int srow[2]; uint32_t soff[2];
#pragma unroll
    for (int it = 0; it < 2; it++) {
        srow[it] = row0 + it * 64;
        soff[it] = (uint32_t)(srow[it] * 16 + ((q ^ ((srow[it] >> 1) & 3)) << 2));
    }

    float acc[4][4][4];
#pragma unroll
    for (int i = 0; i < 4; i++)
#pragma unroll
        for (int j = 0; j < 4; j++)
#pragma unroll
            for (int c = 0; c < 4; c++) acc[i][j][c] = 0.f;

    const uint32_t* gs[4] = {AH, AL, WH, WL};
    const uint4 z4 = make_uint4(0u, 0u, 0u, 0u);
    uint4 pv[4][2];

    // prefetch chunk 0
#pragma unroll
    for (int t = 0; t < 4; t++) {
        const int r0 = (t < 2) ? bm : bn;
        const bool isA = (t < 2);
#pragma unroll
        for (int it = 0; it < 2; it++) {
            const int r = srow[it];
            pv[t][it] = (isA || (bn + r) < N)
                ? *(const uint4*)(gs[t] + (size_t)(r0 + r) * K2 + q * 4) : z4;
        }
    }

    for (int kp0 = 0; kp0 < K2; kp0 += 16) {
        __syncthreads();
#pragma unroll
        for (int t = 0; t < 4; t++)
#pragma unroll
            for (int it = 0; it < 2; it++)
                *(uint4*)&sm[t][soff[it]] = pv[t][it];
        __syncthreads();

        if (kp0 + 16 < K2) {
#pragma unroll
            for (int t = 0; t < 4; t++) {
                const int r0 = (t < 2) ? bm : bn;
                const bool isA = (t < 2);
#pragma unroll
                for (int it = 0; it < 2; it++) {
                    const int r = srow[it];
                    pv[t][it] = (isA || (bn + r) < N)
                        ? *(const uint4*)(gs[t] + (size_t)(r0 + r) * K2 + kp0 + 16 + q * 4) : z4;
                }
            }
        }

#pragma unroll
        for (int ks = 0; ks < 2; ks++) {
            uint32_t aH4[4][4], aL4[4][4];
#pragma unroll
            for (int mt = 0; mt < 4; mt++) {
                ldsm4(aH4[mt], sb         + aoff[ks] + mt * 1024u);
                ldsm4(aL4[mt], sb + 8192u + aoff[ks] + mt * 1024u);
            }
#pragma unroll
            for (int pr = 0; pr < 2; pr++) {
                uint32_t bH4[4], bL4[4];
                ldsm4(bH4, sb + 16384u + boff[pr][ks]);
                ldsm4(bL4, sb + 24576u + boff[pr][ks]);
#pragma unroll
                for (int nt2 = 0; nt2 < 2; nt2++) {
                    const int nt = pr * 2 + nt2;
#pragma unroll
                    for (int mt = 0; mt < 4; mt++) {
                        mma_bf16(acc[mt][nt], aH4[mt], &bH4[nt2*2]);
                        mma_bf16(acc[mt][nt], aH4[mt], &bL4[nt2*2]);
                        mma_bf16(acc[mt][nt], aL4[mt], &bH4[nt2*2]);
                    }
                }
            }
        }
    }

    // epilogue
#pragma unroll
    for (int mt = 0; mt < 4; mt++) {
#pragma unroll
        for (int nt = 0; nt < 4; nt++) {
            const int r = bm + wm + mt*16 + g;
            const int c = bn + wn + nt*8 + tg*2;
            if (c < N) {
                float v[4] = {acc[mt][nt][0], acc[mt][nt][1],
                              acc[mt][nt][2], acc[mt][nt][3]};
                if (EPI == 1) {
                    const float b0 = bias[c], b1 = bias[c+1];
                    v[0] += b0; v[1] += b1; v[2] += b0; v[3] += b1;
#pragma unroll
                    for (int i = 0; i < 4; i++)
                        v[i] = 0.5f * v[i] * (1.f + erff(v[i] * 0.70710678118654752f));
                }
                if (EPI == 2) {
                    const float* r0p = res + (size_t)r * N + c;
                    const float* r1p = res + (size_t)(r+8) * N + c;
                    v[0] += r0p[0]; v[1] += r0p[1]; v[2] += r1p[0]; v[3] += r1p[1];
                }
                *(float2*)(C + (size_t)r     * N + c) = make_float2(v[0], v[1]);
                *(float2*)(C + (size_t)(r+8) * N + c) = make_float2(v[2], v[3]);
            }
        }
    }
}

// ---------------- LayerNorm (512) -> packed bf16 hi/lo -------------------------
__global__ __launch_bounds__(256) void ln_k(
    const float* __restrict__ x, const float* __restrict__ w,
    const float* __restrict__ b, uint32_t* __restrict__ uH,
    uint32_t* __restrict__ uL)
{
    __shared__ float red[256];
    const int row = blockIdx.x;
    const int tid = threadIdx.x;
    const float2 v = ((const float2*)(x + (size_t)row * D_))[tid];

    red[tid] = v.x + v.y;
    __syncthreads();
    for (int st = 128; st > 0; st >>= 1) {
        if (tid < st) red[tid] += red[tid + st];
        __syncthreads();
    }
    const float mean = red[0] * (1.f / D_);
    __syncthreads();
    const float d0 = v.x - mean, d1 = v.y - mean;
    red[tid] = d0*d0 + d1*d1;
    __syncthreads();
    for (int st = 128; st > 0; st >>= 1) {
        if (tid < st) red[tid] += red[tid + st];
        __syncthreads();
    }
    const float rstd = rsqrtf(red[0] * (1.f / D_) + 1e-5f);
    const float2 wv = ((const float2*)w)[tid];
    const float2 bv = ((const float2*)b)[tid];
    uint32_t H, L;
    pack_hl(d0 * rstd * wv.x + bv.x, d1 * rstd * wv.y + bv.y, H, L);
    uH[(size_t)row * (D_/2) + tid] = H;
    uL[(size_t)row * (D_/2) + tid] = L;
}

// ---------------- causal depthwise conv (K=4) + SiLU ---------------------------
__global__ void conv_k(const float* __restrict__ zx, const float* __restrict__ w,
                       const float* __restrict__ bias, float* __restrict__ out)
{
    const int idx = blockIdx.x * blockDim.x + threadIdx.x;
    if (idx >= M_ * CD) return;
    const int c = idx % CD;
    const int m = idx / CD;
    const int t = m % L_;
    float acc = bias[c];
#pragma unroll
    for (int k = 0; k < KC; k++) {
        const int tt = t + k - (KC - 1);
        if (tt >= 0)
            acc = fmaf(zx[(size_t)(m + k - (KC-1)) * DP + DI + c], w[c*KC + k], acc);
    }
    out[idx] = silu_f(acc);
}

// ---------------- dt = softplus(dt+bias); dA = exp(dt * -exp(A_log)) -----------
__global__ void dt_k(const float* __restrict__ zx, const float* __restrict__ dtb,
                     const float* __restrict__ Alog,
                     float* __restrict__ dt, float* __restrict__ dA)
{
    const int idx = blockIdx.x * blockDim.x + threadIdx.x;
    if (idx >= M_ * NH) return;
    const int hh = idx % NH;
    const int m  = idx / NH;
    const float v = zx[(size_t)m * DP + DI + CD + hh] + dtb[hh];
    const float sp = (v > 20.f) ? v : log1pf(expf(v));
    dt[idx] = sp;
    dA[idx] = expf(sp * -expf(Alog[hh]));
}

// ---------------- sequential SSM scan ------------------------------------------
__global__ __launch_bounds__(256) void scan_k(
    const float* __restrict__ xbc, const float* __restrict__ dt,
    const float* __restrict__ dA, const float* __restrict__ Dp,
    float* __restrict__ y)
{
    __shared__ float shB[DS], shC[DS], shX[32], red[256];
    const int psplit = blockIdx.x;
    const int h  = blockIdx.y;
    const int b  = blockIdx.z;
    const int tid = threadIdx.x;
    const int plocal = tid & 31;
    const int ngrp = tid >> 5;
    const int n0 = ngrp * 16;
    const int pg = psplit * 32 + plocal;
    const float Dv = Dp[h];

    float s[16];
#pragma unroll
    for (int j = 0; j < 16; j++) s[j] = 0.f;

    const size_t base = (size_t)b * L_;
    float rB = 0.f, rC = 0.f, rX = 0.f;
    {
        const float* p = xbc + base * CD;
        if (tid < DS) rB = p[DI + tid];
        else          rC = p[DI + DS + (tid - DS)];
        if (tid < 32) rX = p[h*HD + pg];
    }

    for (int t = 0; t < L_; t++) {
        __syncthreads();
        if (tid < DS) shB[tid] = rB; else shC[tid - DS] = rC;
        if (tid < 32) shX[tid] = rX;
        if (t + 1 < L_) {
            const float* p = xbc + (base + t + 1) * CD;
            if (tid < DS) rB = p[DI + tid];
            else          rC = p[DI + DS + (tid - DS)];
            if (tid < 32) rX = p[h*HD + pg];
        }
        const float dAv = dA[(base + t)*NH + h];
        const float dtv = dt[(base + t)*NH + h];
        __syncthreads();

        const float a = dtv * shX[plocal];
        float part = 0.f;
#pragma unroll
        for (int j = 0; j < 16; j++) {
            s[j] = fmaf(s[j], dAv, a * shB[n0 + j]);
            part = fmaf(s[j], shC[n0 + j], part);
        }
        red[ngrp*32 + plocal] = part;
        __syncthreads();
        if (tid < 32) {
            float acc = shX[tid] * Dv;
#pragma unroll
            for (int g2 = 0; g2 < 8; g2++) acc += red[g2*32 + tid];
            y[(base + t)*DI + h*HD + pg] = acc;
        }
    }
}

// ---------------- gating + RMSNorm -> packed bf16 hi/lo ------------------------
__global__ __launch_bounds__(256) void gate_k(
    const float* __restrict__ zx, const float* __restrict__ gw,
    const float* __restrict__ y, uint32_t* __restrict__ yH,
    uint32_t* __restrict__ yL)
{
    __shared__ float red[256];
    const int row = blockIdx.x;
    const int tid = threadIdx.x;
    const float2* zr = (const float2*)(zx + (size_t)row * DP);
    const float2* yr = (const float2*)(y + (size_t)row * DI);
    float g0[2], g1[2]; float ss = 0.f;
#pragma unroll
    for (int i = 0; i < 2; i++) {
        const int p = tid + i*256;
        const float2 z2 = zr[p];
        const float2 y2 = yr[p];
        const float a = y2.x * silu_f(z2.x);
        const float b = y2.y * silu_f(z2.y);
        g0[i] = a; g1[i] = b; ss += a*a + b*b;
    }
    red[tid] = ss;
    __syncthreads();
    for (int st = 128; st > 0; st >>= 1) {
        if (tid < st) red[tid] += red[tid + st];
        __syncthreads();
    }
    const float scale = rsqrtf(red[0] * (1.f / DI) + 1e-5f);
#pragma unroll
    for (int i = 0; i < 2; i++) {
        const int p = tid + i*256;
        const float2 gv = ((const float2*)gw)[p];
        uint32_t H, L;
        pack_hl(g0[i] * scale * gv.x, g1[i] * scale * gv.y, H, L);
        yH[(size_t)row * (DI/2) + p] = H;
        yL[(size_t)row * (DI/2) + p] = L;
    }
}

// ---------------- classifier ---------------------------------------------------
__global__ void cls_k(const float* __restrict__ h, const float* __restrict__ w,
                      const float* __restrict__ b, float* __restrict__ out)
{
    const int gwarp = (blockIdx.x * blockDim.x + threadIdx.x) >> 5;
    const int lane = threadIdx.x & 31;
    if (gwarp >= M_) return;
    const float* hr = h + (size_t)gwarp * D_;
    float a0 = 0.f, a1 = 0.f;
    for (int k = lane; k < D_; k += 32) {
        const float hv = hr[k];
        a0 = fmaf(hv, w[k],      a0);
        a1 = fmaf(hv, w[D_ + k], a1);
    }
    for (int off = 16; off; off >>= 1) {
        a0 += __shfl_xor_sync(0xFFFFFFFFu, a0, off);
        a1 += __shfl_xor_sync(0xFFFFFFFFu, a1, off);
    }
    if (lane == 0) {
        out[gwarp*2 + 0] = a0 + b[0];
        out[gwarp*2 + 1] = a1 + b[1];
    }
}

// ---------------- launch -------------------------------------------------------
extern "C" void kernel_launch(void* const* d_in, const int* in_sizes, int n_in,
                              void* d_out, int out_size)
{
    const float* x      = (const float*)d_in[0];
    const float* fc1_w  = (const float*)d_in[1];
    const float* fc1_b  = (const float*)d_in[2];
    const float* ln_w   = (const float*)d_in[3];
    const float* ln_b   = (const float*)d_in[4];
    const float* in_w   = (const float*)d_in[5];
    const float* conv_w = (const float*)d_in[6];
    const float* conv_b = (const float*)d_in[7];
    const float* dt_b   = (const float*)d_in[8];
    const float* A_log  = (const float*)d_in[9];
    const float* D_p    = (const float*)d_in[10];
    const float* gn_w   = (const float*)d_in[11];
    const float* out_w  = (const float*)d_in[12];
    const float* cls_w  = (const float*)d_in[13];
    const float* cls_b  = (const float*)d_in[14];
    float* out = (float*)d_out;

    float *h, *zx, *xbc, *dtp, *dAp, *y;
    uint32_t *xH, *xL, *uH, *uL, *yH, *yL;
    uint32_t *w1H, *w1L, *wiH, *wiL, *woH, *woL;
    cudaGetSymbolAddress((void**)&h,   g_h);
    cudaGetSymbolAddress((void**)&zx,  g_zx);
    cudaGetSymbolAddress((void**)&xbc, g_xbc);
    cudaGetSymbolAddress((void**)&dtp, g_dt);
    cudaGetSymbolAddress((void**)&dAp, g_dA);
    cudaGetSymbolAddress((void**)&y,   g_y);
    cudaGetSymbolAddress((void**)&xH,  g_xH);
    cudaGetSymbolAddress((void**)&xL,  g_xL);
    cudaGetSymbolAddress((void**)&uH,  g_uH);
    cudaGetSymbolAddress((void**)&uL,  g_uL);
    cudaGetSymbolAddress((void**)&yH,  g_yH);
    cudaGetSymbolAddress((void**)&yL,  g_yL);
    cudaGetSymbolAddress((void**)&w1H, g_w1H);
    cudaGetSymbolAddress((void**)&w1L, g_w1L);
    cudaGetSymbolAddress((void**)&wiH, g_wiH);
    cudaGetSymbolAddress((void**)&wiL, g_wiL);
    cudaGetSymbolAddress((void**)&woH, g_woH);
    cudaGetSymbolAddress((void**)&woL, g_woL);

    // weight + input conversions (cheap, memory-bound)
    { int n = D_*IN_/2;      cvt_k<<<(n+255)/256, 256>>>(fc1_w, w1H, w1L, n); }
    { int n = NL*DP*D_/2;    cvt_k<<<(n+255)/256, 256>>>(in_w,  wiH, wiL, n); }
    { int n = NL*D_*DI/2;    cvt_k<<<(n+255)/256, 256>>>(out_w, woH, woL, n); }
    { int n = M_*IN_/2;      cvt_k<<<(n+255)/256, 256>>>(x,     xH,  xL,  n); }

    // fc1 + GELU
    gemm_ls<1><<<dim3(D_/128, M_/128), 256>>>(
        xH, xL, w1H, w1L, fc1_b, nullptr, h, M_, D_, IN_);

    for (int l = 0; l < NL; l++) {
        ln_k<<<M_, 256>>>(h, ln_w + l*D_, ln_b + l*D_, uH, uL);
        gemm_ls<0><<<dim3((DP + 127)/128, M_/128), 256>>>(
            uH, uL, wiH + (size_t)l*DP*(D_/2), wiL + (size_t)l*DP*(D_/2),
            nullptr, nullptr, zx, M_, DP, D_);
        conv_k<<<(M_*CD + 255)/256, 256>>>(zx, conv_w + l*CD*KC, conv_b + l*CD, xbc);
        dt_k<<<(M_*NH + 255)/256, 256>>>(zx, dt_b + l*NH, A_log + l*NH, dtp, dAp);
        scan_k<<<dim3(2, NH, B_), 256>>>(xbc, dtp, dAp, D_p + l*NH, y);
        gate_k<<<M_, 256>>>(zx, gn_w + l*DI, y, yH, yL);
        gemm_ls<2><<<dim3(D_/128, M_/128), 256>>>(
            yH, yL, woH + (size_t)l*D_*(DI/2), woL + (size_t)l*D_*(DI/2),
            nullptr, h, h, M_, D_, DI);
    }

    cls_k<<<(M_*32 + 255)/256, 256>>>(h, cls_w, cls_b, out);
}